// round 4
// baseline (speedup 1.0000x reference)
#include <cuda_runtime.h>

#define T_STEPS 240
#define H       25
#define BLK     128      // 4 warps/block, 2 batches/warp -> 8 batches/block

// ---------------------------------------------------------------------------
// MUFU-based activations (~1e-7 rel err; exact at saturation).
// ---------------------------------------------------------------------------
__device__ __forceinline__ float sigmoid_f(float x) {
    float e = __expf(-x);
    return __fdividef(1.f, 1.f + e);
}
__device__ __forceinline__ float tanh_f(float x) {
    float e = __expf(-2.f * x);
    return __fdividef(2.f, 1.f + e) - 1.f;
}

// Repeat a macro for K = 0..24 (hidden size)
#define R25(M) M(0) M(1) M(2) M(3) M(4) M(5) M(6) M(7) M(8) M(9) M(10) M(11) \
               M(12) M(13) M(14) M(15) M(16) M(17) M(18) M(19) M(20) M(21) M(22) M(23) M(24)

// Named weight registers: lane j holds W_hh[(g*H+j)][k] for all k, all 4 gates.
#define DECL_W(K) float wi##K, wf##K, wg##K, wo##K;

#define LOAD_W(K)                                                     \
    wi##K = lv ? __ldg(&W_hh[(0 * H + jc) * H + K]) : 0.f;            \
    wf##K = lv ? __ldg(&W_hh[(1 * H + jc) * H + K]) : 0.f;            \
    wg##K = lv ? __ldg(&W_hh[(2 * H + jc) * H + K]) : 0.f;            \
    wo##K = lv ? __ldg(&W_hh[(3 * H + jc) * H + K]) : 0.f;

// One k-slice of the recurrent matvec: broadcast h[K], 8 FMAs (2 batches x 4 gates).
#define GATE_K(K)                                                     \
    hk0 = __shfl_sync(0xffffffffu, h0, K);                            \
    hk1 = __shfl_sync(0xffffffffu, h1, K);                            \
    ai0 = fmaf(hk0, wi##K, ai0);  af0 = fmaf(hk0, wf##K, af0);        \
    ag0 = fmaf(hk0, wg##K, ag0);  ao0 = fmaf(hk0, wo##K, ao0);        \
    ai1 = fmaf(hk1, wi##K, ai1);  af1 = fmaf(hk1, wf##K, af1);        \
    ag1 = fmaf(hk1, wg##K, ag1);  ao1 = fmaf(hk1, wo##K, ao1);

#define LSTM_STEP(XV0, XV1) do {                                      \
    float ai0 = fmaf((XV0), wih_i, bias_i);                           \
    float af0 = fmaf((XV0), wih_f, bias_f);                           \
    float ag0 = fmaf((XV0), wih_g, bias_g);                           \
    float ao0 = fmaf((XV0), wih_o, bias_o);                           \
    float ai1 = fmaf((XV1), wih_i, bias_i);                           \
    float af1 = fmaf((XV1), wih_f, bias_f);                           \
    float ag1 = fmaf((XV1), wih_g, bias_g);                           \
    float ao1 = fmaf((XV1), wih_o, bias_o);                           \
    float hk0, hk1;                                                   \
    R25(GATE_K)                                                       \
    float ig = sigmoid_f(ai0), fg = sigmoid_f(af0);                   \
    float gg = tanh_f(ag0),    og = sigmoid_f(ao0);                   \
    c0 = fmaf(fg, c0, ig * gg);                                       \
    h0 = og * tanh_f(c0);                                             \
    ig = sigmoid_f(ai1); fg = sigmoid_f(af1);                         \
    gg = tanh_f(ag1);    og = sigmoid_f(ao1);                         \
    c1 = fmaf(fg, c1, ig * gg);                                       \
    h1 = og * tanh_f(c1);                                             \
} while (0)

__global__ void __launch_bounds__(BLK) lstm_kernel(
    const float* __restrict__ x,      // [B, T, 1]
    const float* __restrict__ W_ih,   // [4H, 1]
    const float* __restrict__ W_hh,   // [4H, H]
    const float* __restrict__ b_ih,   // [4H]
    const float* __restrict__ b_hh,   // [4H]
    const float* __restrict__ W_fc,   // [2, H]
    const float* __restrict__ b_fc,   // [2]
    float* __restrict__ out,          // [B, 2]
    int B)
{
    const int lane = threadIdx.x & 31;
    const int warpGlobal = (blockIdx.x * BLK + threadIdx.x) >> 5;

    const int  j  = lane;
    const bool lv = (j < H);           // lanes 25..31 idle (zero weights -> h stays 0)
    const int  jc = lv ? j : (H - 1);  // clamped row index for safe addressing

    // Two batch elements per warp; clamp for loads, guard writes.
    int b0 = 2 * warpGlobal;
    int b1 = 2 * warpGlobal + 1;
    const bool v0 = (b0 < B), v1 = (b1 < B);
    if (!v0) b0 = B - 1;
    if (!v1) b1 = B - 1;

    // ---- register-resident weights (named scalars; cannot spill) ----
    R25(DECL_W)
    R25(LOAD_W)

    const float wih_i = lv ? __ldg(&W_ih[0 * H + jc]) : 0.f;
    const float wih_f = lv ? __ldg(&W_ih[1 * H + jc]) : 0.f;
    const float wih_g = lv ? __ldg(&W_ih[2 * H + jc]) : 0.f;
    const float wih_o = lv ? __ldg(&W_ih[3 * H + jc]) : 0.f;
    const float bias_i = lv ? __ldg(&b_ih[0 * H + jc]) + __ldg(&b_hh[0 * H + jc]) : 0.f;
    const float bias_f = lv ? __ldg(&b_ih[1 * H + jc]) + __ldg(&b_hh[1 * H + jc]) : 0.f;
    const float bias_g = lv ? __ldg(&b_ih[2 * H + jc]) + __ldg(&b_hh[2 * H + jc]) : 0.f;
    const float bias_o = lv ? __ldg(&b_ih[3 * H + jc]) + __ldg(&b_hh[3 * H + jc]) : 0.f;

    // ---- recurrence; h,c are scalar registers per lane ----
    float h0 = 0.f, c0 = 0.f, h1 = 0.f, c1 = 0.f;

    const float4* xq0p = reinterpret_cast<const float4*>(x + (size_t)b0 * T_STEPS);
    const float4* xq1p = reinterpret_cast<const float4*>(x + (size_t)b1 * T_STEPS);

#pragma unroll 1
    for (int t4 = 0; t4 < T_STEPS / 4; t4++) {
        float4 xq0 = __ldg(xq0p + t4);   // warp-uniform address: 1 sector/req
        float4 xq1 = __ldg(xq1p + t4);
        LSTM_STEP(xq0.x, xq1.x);
        LSTM_STEP(xq0.y, xq1.y);
        LSTM_STEP(xq0.z, xq1.z);
        LSTM_STEP(xq0.w, xq1.w);
    }

    // ---- FC head: warp-reduce h . W_fc^T (idle lanes contribute h=0) ----
    const float wfc0 = lv ? __ldg(&W_fc[jc])     : 0.f;
    const float wfc1 = lv ? __ldg(&W_fc[H + jc]) : 0.f;
    float s00 = h0 * wfc0, s01 = h0 * wfc1;
    float s10 = h1 * wfc0, s11 = h1 * wfc1;
#pragma unroll
    for (int off = 16; off > 0; off >>= 1) {
        s00 += __shfl_xor_sync(0xffffffffu, s00, off);
        s01 += __shfl_xor_sync(0xffffffffu, s01, off);
        s10 += __shfl_xor_sync(0xffffffffu, s10, off);
        s11 += __shfl_xor_sync(0xffffffffu, s11, off);
    }
    if (lane == 0) {
        const float bf0 = __ldg(&b_fc[0]), bf1 = __ldg(&b_fc[1]);
        if (v0) {
            out[(size_t)b0 * 2 + 0] = s00 + bf0;
            out[(size_t)b0 * 2 + 1] = s01 + bf1;
        }
        if (v1) {
            out[(size_t)b1 * 2 + 0] = s10 + bf0;
            out[(size_t)b1 * 2 + 1] = s11 + bf1;
        }
    }
}

extern "C" void kernel_launch(void* const* d_in, const int* in_sizes, int n_in,
                              void* d_out, int out_size) {
    const float* x    = (const float*)d_in[0];
    const float* W_ih = (const float*)d_in[1];
    const float* W_hh = (const float*)d_in[2];
    const float* b_ih = (const float*)d_in[3];
    const float* b_hh = (const float*)d_in[4];
    const float* W_fc = (const float*)d_in[5];
    const float* b_fc = (const float*)d_in[6];

    int B = in_sizes[0] / T_STEPS;           // x is [B, T, 1]
    int warpsNeeded  = (B + 1) / 2;          // 2 batches per warp
    int blocks       = (warpsNeeded * 32 + BLK - 1) / BLK;

    lstm_kernel<<<blocks, BLK>>>(x, W_ih, W_hh, b_ih, b_hh, W_fc, b_fc,
                                 (float*)d_out, B);
}

// round 5
// speedup vs baseline: 1.1148x; 1.1148x over previous
#include <cuda_runtime.h>

#define T_STEPS 240
#define H       25
#define BLK     128
#define WPB     (BLK / 32)

typedef unsigned long long u64;

// ---------------------------------------------------------------------------
// Packed f32x2 helpers (Blackwell)
// ---------------------------------------------------------------------------
__device__ __forceinline__ u64 pack2(float lo, float hi) {
    u64 r;
    asm("mov.b64 %0, {%1, %2};" : "=l"(r) : "f"(lo), "f"(hi));
    return r;
}
__device__ __forceinline__ float unpack_sum(u64 v) {
    float lo, hi;
    asm("mov.b64 {%0, %1}, %2;" : "=f"(lo), "=f"(hi) : "l"(v));
    return lo + hi;
}
#define FFMA2(acc, h, w) \
    asm("fma.rn.f32x2 %0, %1, %2, %0;" : "+l"(acc) : "l"(h), "l"(w))

// MUFU-based activations (~1e-7 rel err; exact at saturation).
__device__ __forceinline__ float sigmoid_f(float x) {
    float e = __expf(-x);
    return __fdividef(1.f, 1.f + e);
}
__device__ __forceinline__ float tanh_f(float x) {
    float e = __expf(-2.f * x);
    return __fdividef(2.f, 1.f + e) - 1.f;
}

// Repeat for packed-k indices 0..12 (k pairs (0,1)..(24,25); k=25 padded to 0)
#define R13(M) M(0) M(1) M(2) M(3) M(4) M(5) M(6) M(7) M(8) M(9) M(10) M(11) M(12)

#define DECL_WP(Q) u64 wi##Q, wf##Q, wg##Q, wo##Q;

#define LOAD_WP(Q) {                                                          \
    const int k0 = 2 * (Q), k1 = 2 * (Q) + 1;                                 \
    float a, b;                                                               \
    a = (lv && k0 < H) ? __ldg(&W_hh[(0 * H + jc) * H + k0]) : 0.f;           \
    b = (lv && k1 < H) ? __ldg(&W_hh[(0 * H + jc) * H + k1]) : 0.f;           \
    wi##Q = pack2(a, b);                                                      \
    a = (lv && k0 < H) ? __ldg(&W_hh[(1 * H + jc) * H + k0]) : 0.f;           \
    b = (lv && k1 < H) ? __ldg(&W_hh[(1 * H + jc) * H + k1]) : 0.f;           \
    wf##Q = pack2(a, b);                                                      \
    a = (lv && k0 < H) ? __ldg(&W_hh[(2 * H + jc) * H + k0]) : 0.f;           \
    b = (lv && k1 < H) ? __ldg(&W_hh[(2 * H + jc) * H + k1]) : 0.f;           \
    wg##Q = pack2(a, b);                                                      \
    a = (lv && k0 < H) ? __ldg(&W_hh[(3 * H + jc) * H + k0]) : 0.f;           \
    b = (lv && k1 < H) ? __ldg(&W_hh[(3 * H + jc) * H + k1]) : 0.f;           \
    wo##Q = pack2(a, b);                                                      \
}

// 4 packed-gate FMAs for one packed h pair. S = batch (0/1), P = pair index.
#define GP(S, V, P)                                                           \
    FFMA2(ai##S, (V), wi##P); FFMA2(af##S, (V), wf##P);                       \
    FFMA2(ag##S, (V), wg##P); FFMA2(ao##S, (V), wo##P);

// One LSTM timestep for both batches. B0/B1 = this step's h-broadcast buffers
// (parity double-buffered by caller). h in smem as 28 scalars -> packed pairs
// read via LDS.128 at warp-uniform (broadcast) addresses.
#define LSTM_STEP(B0, B1, XV0, XV1) do {                                      \
    if (lane < 28) { (B0)[lane] = h0; (B1)[lane] = h1; }                      \
    __syncwarp();                                                             \
    u64 ai0 = 0, af0 = 0, ag0 = 0, ao0 = 0;                                   \
    u64 ai1 = 0, af1 = 0, ag1 = 0, ao1 = 0;                                   \
    { ulonglong2 A = *reinterpret_cast<const ulonglong2*>((B0) + 0);          \
      ulonglong2 C = *reinterpret_cast<const ulonglong2*>((B1) + 0);          \
      GP(0, A.x, 0) GP(0, A.y, 1) GP(1, C.x, 0) GP(1, C.y, 1) }               \
    { ulonglong2 A = *reinterpret_cast<const ulonglong2*>((B0) + 4);          \
      ulonglong2 C = *reinterpret_cast<const ulonglong2*>((B1) + 4);          \
      GP(0, A.x, 2) GP(0, A.y, 3) GP(1, C.x, 2) GP(1, C.y, 3) }               \
    { ulonglong2 A = *reinterpret_cast<const ulonglong2*>((B0) + 8);          \
      ulonglong2 C = *reinterpret_cast<const ulonglong2*>((B1) + 8);          \
      GP(0, A.x, 4) GP(0, A.y, 5) GP(1, C.x, 4) GP(1, C.y, 5) }               \
    { ulonglong2 A = *reinterpret_cast<const ulonglong2*>((B0) + 12);         \
      ulonglong2 C = *reinterpret_cast<const ulonglong2*>((B1) + 12);         \
      GP(0, A.x, 6) GP(0, A.y, 7) GP(1, C.x, 6) GP(1, C.y, 7) }               \
    { ulonglong2 A = *reinterpret_cast<const ulonglong2*>((B0) + 16);         \
      ulonglong2 C = *reinterpret_cast<const ulonglong2*>((B1) + 16);         \
      GP(0, A.x, 8) GP(0, A.y, 9) GP(1, C.x, 8) GP(1, C.y, 9) }               \
    { ulonglong2 A = *reinterpret_cast<const ulonglong2*>((B0) + 20);         \
      ulonglong2 C = *reinterpret_cast<const ulonglong2*>((B1) + 20);         \
      GP(0, A.x, 10) GP(0, A.y, 11) GP(1, C.x, 10) GP(1, C.y, 11) }           \
    { u64 A = *reinterpret_cast<const u64*>((B0) + 24);                       \
      u64 C = *reinterpret_cast<const u64*>((B1) + 24);                       \
      GP(0, A, 12) GP(1, C, 12) }                                             \
    float vi0 = unpack_sum(ai0) + fmaf((XV0), wih_i, bias_i);                 \
    float vf0 = unpack_sum(af0) + fmaf((XV0), wih_f, bias_f);                 \
    float vg0 = unpack_sum(ag0) + fmaf((XV0), wih_g, bias_g);                 \
    float vo0 = unpack_sum(ao0) + fmaf((XV0), wih_o, bias_o);                 \
    float vi1 = unpack_sum(ai1) + fmaf((XV1), wih_i, bias_i);                 \
    float vf1 = unpack_sum(af1) + fmaf((XV1), wih_f, bias_f);                 \
    float vg1 = unpack_sum(ag1) + fmaf((XV1), wih_g, bias_g);                 \
    float vo1 = unpack_sum(ao1) + fmaf((XV1), wih_o, bias_o);                 \
    float ig = sigmoid_f(vi0), fg = sigmoid_f(vf0);                           \
    float gg = tanh_f(vg0),    og = sigmoid_f(vo0);                           \
    c0 = fmaf(fg, c0, ig * gg);  h0 = og * tanh_f(c0);                        \
    ig = sigmoid_f(vi1); fg = sigmoid_f(vf1);                                 \
    gg = tanh_f(vg1);    og = sigmoid_f(vo1);                                 \
    c1 = fmaf(fg, c1, ig * gg);  h1 = og * tanh_f(c1);                        \
} while (0)

__global__ void __launch_bounds__(BLK) lstm_kernel(
    const float* __restrict__ x,      // [B, T, 1]
    const float* __restrict__ W_ih,   // [4H, 1]
    const float* __restrict__ W_hh,   // [4H, H]
    const float* __restrict__ b_ih,   // [4H]
    const float* __restrict__ b_hh,   // [4H]
    const float* __restrict__ W_fc,   // [2, H]
    const float* __restrict__ b_fc,   // [2]
    float* __restrict__ out,          // [B, 2]
    int B)
{
    // h-broadcast buffers: [warp][parity][batch][28 units] (pads written as 0
    // by lanes 25-27, whose zero weights/biases keep their h exactly 0).
    __shared__ __align__(16) float hb[WPB][2][2][28];

    const int lane = threadIdx.x & 31;
    const int wIn  = threadIdx.x >> 5;
    const int warpGlobal = (blockIdx.x * BLK + threadIdx.x) >> 5;

    const bool lv = (lane < H);
    const int  jc = lv ? lane : (H - 1);

    int b0 = 2 * warpGlobal;
    int b1 = 2 * warpGlobal + 1;
    const bool v0 = (b0 < B), v1 = (b1 < B);
    if (!v0) b0 = B - 1;
    if (!v1) b1 = B - 1;

    // K-packed recurrent weights: 52 named u64 SSA values (cannot be demoted).
    R13(DECL_WP)
    R13(LOAD_WP)

    const float wih_i = lv ? __ldg(&W_ih[0 * H + jc]) : 0.f;
    const float wih_f = lv ? __ldg(&W_ih[1 * H + jc]) : 0.f;
    const float wih_g = lv ? __ldg(&W_ih[2 * H + jc]) : 0.f;
    const float wih_o = lv ? __ldg(&W_ih[3 * H + jc]) : 0.f;
    const float bias_i = lv ? __ldg(&b_ih[0 * H + jc]) + __ldg(&b_hh[0 * H + jc]) : 0.f;
    const float bias_f = lv ? __ldg(&b_ih[1 * H + jc]) + __ldg(&b_hh[1 * H + jc]) : 0.f;
    const float bias_g = lv ? __ldg(&b_ih[2 * H + jc]) + __ldg(&b_hh[2 * H + jc]) : 0.f;
    const float bias_o = lv ? __ldg(&b_ih[3 * H + jc]) + __ldg(&b_hh[3 * H + jc]) : 0.f;

    float* bA0 = &hb[wIn][0][0][0];
    float* bA1 = &hb[wIn][0][1][0];
    float* bB0 = &hb[wIn][1][0][0];
    float* bB1 = &hb[wIn][1][1][0];

    float h0 = 0.f, c0 = 0.f, h1 = 0.f, c1 = 0.f;

    const float4* xq0p = reinterpret_cast<const float4*>(x + (size_t)b0 * T_STEPS);
    const float4* xq1p = reinterpret_cast<const float4*>(x + (size_t)b1 * T_STEPS);

#pragma unroll 1
    for (int t4 = 0; t4 < T_STEPS / 4; t4++) {
        float4 xq0 = __ldg(xq0p + t4);   // warp-uniform broadcast loads
        float4 xq1 = __ldg(xq1p + t4);
        LSTM_STEP(bA0, bA1, xq0.x, xq1.x);
        LSTM_STEP(bB0, bB1, xq0.y, xq1.y);
        LSTM_STEP(bA0, bA1, xq0.z, xq1.z);
        LSTM_STEP(bB0, bB1, xq0.w, xq1.w);
    }

    // FC head: warp-reduce h . W_fc^T (idle lanes contribute h=0)
    const float wfc0 = lv ? __ldg(&W_fc[jc])     : 0.f;
    const float wfc1 = lv ? __ldg(&W_fc[H + jc]) : 0.f;
    float s00 = h0 * wfc0, s01 = h0 * wfc1;
    float s10 = h1 * wfc0, s11 = h1 * wfc1;
#pragma unroll
    for (int off = 16; off > 0; off >>= 1) {
        s00 += __shfl_xor_sync(0xffffffffu, s00, off);
        s01 += __shfl_xor_sync(0xffffffffu, s01, off);
        s10 += __shfl_xor_sync(0xffffffffu, s10, off);
        s11 += __shfl_xor_sync(0xffffffffu, s11, off);
    }
    if (lane == 0) {
        const float bf0 = __ldg(&b_fc[0]), bf1 = __ldg(&b_fc[1]);
        if (v0) {
            out[(size_t)b0 * 2 + 0] = s00 + bf0;
            out[(size_t)b0 * 2 + 1] = s01 + bf1;
        }
        if (v1) {
            out[(size_t)b1 * 2 + 0] = s10 + bf0;
            out[(size_t)b1 * 2 + 1] = s11 + bf1;
        }
    }
}

extern "C" void kernel_launch(void* const* d_in, const int* in_sizes, int n_in,
                              void* d_out, int out_size) {
    const float* x    = (const float*)d_in[0];
    const float* W_ih = (const float*)d_in[1];
    const float* W_hh = (const float*)d_in[2];
    const float* b_ih = (const float*)d_in[3];
    const float* b_hh = (const float*)d_in[4];
    const float* W_fc = (const float*)d_in[5];
    const float* b_fc = (const float*)d_in[6];

    int B = in_sizes[0] / T_STEPS;          // x is [B, T, 1]
    int warpsNeeded = (B + 1) / 2;          // 2 batches per warp
    int blocks      = (warpsNeeded * 32 + BLK - 1) / BLK;

    lstm_kernel<<<blocks, BLK>>>(x, W_ih, W_hh, b_ih, b_hh, W_fc, b_fc,
                                 (float*)d_out, B);
}